// round 2
// baseline (speedup 1.0000x reference)
#include <cuda_runtime.h>

// DWTExtractor: 2-level Haar DWT + bilinear 2x upsample of level-2 details.
// Input:  (32, 1, 1024, 1024) fp32
// Output: (32, 6, 512, 512) fp32 = [cH1, cV1, cD1, up(cH2), up(cV2), up(cD2)]
//
// Single fused kernel: each block handles a 64x64 output tile (all 6 channels)
// for one batch image.
//   Phase 1: compute cA1 over a 68x68 tile (2-halo) from input (float2 loads),
//            write cH1/cV1/cD1 for the central 64x64 straight to gmem.
//   Phase 2: compute cH2/cV2/cD2 over 34x34 (1-halo at the 256-grid), with
//            edge clamping baked in (== jax resize weight renormalization).
//   Phase 3: separable half-pixel bilinear 2x (weights 0.75/0.25), write
//            channels 3,4,5.

#define TS    64   // output tile edge
#define CA_T  68   // cA1 tile edge (64 + 2 halo each side)
#define CA_S  69   // cA1 smem row stride
#define H2_T  34   // level-2 tile edge (32 + 1 halo each side)
#define H2_S  35   // level-2 smem row stride

__global__ __launch_bounds__(256, 4)
void dwt_fused_kernel(const float* __restrict__ in, float* __restrict__ out)
{
    __shared__ float sA[CA_T * CA_S];
    __shared__ float sH[H2_T * H2_S];
    __shared__ float sV[H2_T * H2_S];
    __shared__ float sD[H2_T * H2_S];

    const int b   = blockIdx.z;
    const int oy0 = blockIdx.y * TS;   // tile origin in the 512x512 output grid
    const int ox0 = blockIdx.x * TS;
    const int tid = threadIdx.x;

    const float* __restrict__ inb  = in  + (size_t)b * 1024 * 1024;
    float* __restrict__       outb = out + (size_t)b * 6 * 512 * 512;

    // ---- Phase 1: cA1 tile (68x68), level-1 coords [oy0-2, oy0+65] ----
    #pragma unroll 1
    for (int i = tid; i < CA_T * CA_T; i += 256) {
        const int ly = i / CA_T;
        const int lc = i - ly * CA_T;
        const int y1 = oy0 - 2 + ly;           // level-1 (512-grid) coords
        const int x1 = ox0 - 2 + lc;
        const int y1c = min(max(y1, 0), 511);  // only matters at image border;
        const int x1c = min(max(x1, 0), 511);  // those cA1 values are never used

        const float2* r0 = (const float2*)(inb + (size_t)(2 * y1c)     * 1024);
        const float2* r1 = (const float2*)(inb + (size_t)(2 * y1c + 1) * 1024);
        const float2 t = r0[x1c];
        const float2 u = r1[x1c];

        sA[ly * CA_S + lc] = (t.x + t.y + u.x + u.y) * 0.5f;

        // central 64x64: emit level-1 detail channels directly
        if ((unsigned)(ly - 2) < (unsigned)TS && (unsigned)(lc - 2) < (unsigned)TS) {
            const float h = (t.x - t.y + u.x - u.y) * 0.5f;
            const float v = (t.x + t.y - u.x - u.y) * 0.5f;
            const float d = (t.x - t.y - u.x + u.y) * 0.5f;
            const size_t o = (size_t)y1 * 512 + x1;
            outb[0 * 262144 + o] = h;
            outb[1 * 262144 + o] = v;
            outb[2 * 262144 + o] = d;
        }
    }
    __syncthreads();

    // ---- Phase 2: level-2 details (34x34), clamp indices at 256-grid edges ----
    const int r0g = oy0 >> 1;  // level-2 tile origin (256 grid)
    const int c0g = ox0 >> 1;
    #pragma unroll 1
    for (int i = tid; i < H2_T * H2_T; i += 256) {
        const int lr = i / H2_T;
        const int lc = i - lr * H2_T;
        const int r = min(max(r0g - 1 + lr, 0), 255);
        const int c = min(max(c0g - 1 + lc, 0), 255);
        const int ay = 2 * r - (oy0 - 2);   // local row in sA (in [0,66])
        const int ax = 2 * c - (ox0 - 2);
        const float a00 = sA[ay * CA_S + ax];
        const float a01 = sA[ay * CA_S + ax + 1];
        const float a10 = sA[(ay + 1) * CA_S + ax];
        const float a11 = sA[(ay + 1) * CA_S + ax + 1];
        sH[lr * H2_S + lc] = (a00 - a01 + a10 - a11) * 0.5f;
        sV[lr * H2_S + lc] = (a00 + a01 - a10 - a11) * 0.5f;
        sD[lr * H2_S + lc] = (a00 - a01 - a10 + a11) * 0.5f;
    }
    __syncthreads();

    // ---- Phase 3: half-pixel bilinear 2x upsample, channels 3,4,5 ----
    // out[2k]   = 0.25*v[k-1] + 0.75*v[k]
    // out[2k+1] = 0.75*v[k]   + 0.25*v[k+1]
    #pragma unroll 1
    for (int i = tid; i < TS * TS; i += 256) {
        const int y = i >> 6;        // local output row (0..63)
        const int x = i & 63;        // local output col
        const int ky = (y >> 1) + 1; // local index of k in the 34-row tile
        const int kx = (x >> 1) + 1;

        const int   ry0 = (y & 1) ? ky     : ky - 1;
        const int   ry1 = (y & 1) ? ky + 1 : ky;
        const float wy0 = (y & 1) ? 0.75f  : 0.25f;
        const float wy1 = 1.0f - wy0;
        const int   cx0 = (x & 1) ? kx     : kx - 1;
        const int   cx1 = (x & 1) ? kx + 1 : kx;
        const float wx0 = (x & 1) ? 0.75f  : 0.25f;
        const float wx1 = 1.0f - wx0;

        const int i00 = ry0 * H2_S + cx0;
        const int i01 = ry0 * H2_S + cx1;
        const int i10 = ry1 * H2_S + cx0;
        const int i11 = ry1 * H2_S + cx1;

        const float h = wy0 * (wx0 * sH[i00] + wx1 * sH[i01])
                      + wy1 * (wx0 * sH[i10] + wx1 * sH[i11]);
        const float v = wy0 * (wx0 * sV[i00] + wx1 * sV[i01])
                      + wy1 * (wx0 * sV[i10] + wx1 * sV[i11]);
        const float d = wy0 * (wx0 * sD[i00] + wx1 * sD[i01])
                      + wy1 * (wx0 * sD[i10] + wx1 * sD[i11]);

        const size_t o = (size_t)(oy0 + y) * 512 + (ox0 + x);
        outb[3 * 262144 + o] = h;
        outb[4 * 262144 + o] = v;
        outb[5 * 262144 + o] = d;
    }
}

extern "C" void kernel_launch(void* const* d_in, const int* in_sizes, int n_in,
                              void* d_out, int out_size)
{
    const float* x = (const float*)d_in[0];
    float* out = (float*)d_out;
    dim3 grid(512 / TS, 512 / TS, 32);   // (8, 8, 32) = 2048 blocks
    dwt_fused_kernel<<<grid, 256>>>(x, out);
}

// round 3
// speedup vs baseline: 1.3076x; 1.3076x over previous
#include <cuda_runtime.h>

// DWTExtractor: 2-level Haar DWT + bilinear 2x upsample of level-2 details.
// Input:  (32, 1, 1024, 1024) fp32
// Output: (32, 6, 512, 512) fp32 = [cH1, cV1, cD1, up(cH2), up(cV2), up(cD2)]
//
// Each block: one 64x64 output tile (all 6 channels) for one batch image.
//   Phase A: level-2 details (34x34 incl. 1-halo) computed DIRECTLY from the
//            input (4x4 float4 region per cell; L1/L2 hits) into smem.
//            Edge clamping == jax resize weight renormalization.
//   Phase B: level-1 details, 4 cells/thread, float4 loads + float4 streaming
//            stores, no smem, no clamps, shift-only indexing.
//   (one __syncthreads)
//   Phase C: separable half-pixel bilinear 2x (0.75/0.25), 4 outputs/thread,
//            float4 streaming stores.

#define TS    64
#define H2_T  34
#define H2_S  35

__global__ __launch_bounds__(256, 6)
void dwt_fused_kernel(const float* __restrict__ in, float* __restrict__ out)
{
    __shared__ float sH[H2_T * H2_S];
    __shared__ float sV[H2_T * H2_S];
    __shared__ float sD[H2_T * H2_S];

    const int b   = blockIdx.z;
    const int oy0 = blockIdx.y * TS;
    const int ox0 = blockIdx.x * TS;
    const int tid = threadIdx.x;

    const float* __restrict__ inb  = in  + (size_t)b * 1024 * 1024;
    float* __restrict__       outb = out + (size_t)b * 6 * 512 * 512;

    // ---- Phase A: level-2 details (34x34 with halo) from input directly ----
    // cell (r,c) on the 256-grid <- input rows 4r..4r+3, cols 4c..4c+3
    const int r0g = oy0 >> 1;
    const int c0g = ox0 >> 1;
    #pragma unroll 1
    for (int i = tid; i < H2_T * H2_T; i += 256) {
        const int lr = i / H2_T;
        const int lc = i - lr * H2_T;
        const int r = min(max(r0g - 1 + lr, 0), 255);
        const int c = min(max(c0g - 1 + lc, 0), 255);

        const float4 v0 = *((const float4*)(inb + (size_t)(4 * r    ) * 1024) + c);
        const float4 v1 = *((const float4*)(inb + (size_t)(4 * r + 1) * 1024) + c);
        const float4 v2 = *((const float4*)(inb + (size_t)(4 * r + 2) * 1024) + c);
        const float4 v3 = *((const float4*)(inb + (size_t)(4 * r + 3) * 1024) + c);

        // horizontal pair sums per row
        const float p0 = v0.x + v0.y, q0 = v0.z + v0.w;
        const float p1 = v1.x + v1.y, q1 = v1.z + v1.w;
        const float p2 = v2.x + v2.y, q2 = v2.z + v2.w;
        const float p3 = v3.x + v3.y, q3 = v3.z + v3.w;
        // 2*cA1 quad: a00=p0+p1, a01=q0+q1, a10=p2+p3, a11=q2+q3
        const float a00 = p0 + p1, a01 = q0 + q1;
        const float a10 = p2 + p3, a11 = q2 + q3;
        // level-2 coeffs: 0.5 (haar2) * 0.5 (cA1 factor folded) = 0.25
        sH[lr * H2_S + lc] = (a00 - a01 + a10 - a11) * 0.25f;
        sV[lr * H2_S + lc] = (a00 + a01 - a10 - a11) * 0.25f;
        sD[lr * H2_S + lc] = (a00 - a01 - a10 + a11) * 0.25f;
    }

    // ---- Phase B: level-1 details, 4 horizontally-adjacent cells/thread ----
    #pragma unroll 1
    for (int i = tid; i < 1024; i += 256) {
        const int y  = i >> 4;           // 0..63
        const int xg = (i & 15) << 2;    // 0,4,...,60
        const int y1 = oy0 + y;
        const int x1 = ox0 + xg;

        const float4* rt = (const float4*)(inb + (size_t)(2 * y1    ) * 1024) + (x1 >> 1);
        const float4* ru = (const float4*)(inb + (size_t)(2 * y1 + 1) * 1024) + (x1 >> 1);
        const float4 t0 = rt[0], t1 = rt[1];
        const float4 u0 = ru[0], u1 = ru[1];

        float4 h, v, d;
        h.x = (t0.x - t0.y + u0.x - u0.y) * 0.5f;
        v.x = (t0.x + t0.y - u0.x - u0.y) * 0.5f;
        d.x = (t0.x - t0.y - u0.x + u0.y) * 0.5f;
        h.y = (t0.z - t0.w + u0.z - u0.w) * 0.5f;
        v.y = (t0.z + t0.w - u0.z - u0.w) * 0.5f;
        d.y = (t0.z - t0.w - u0.z + u0.w) * 0.5f;
        h.z = (t1.x - t1.y + u1.x - u1.y) * 0.5f;
        v.z = (t1.x + t1.y - u1.x - u1.y) * 0.5f;
        d.z = (t1.x - t1.y - u1.x + u1.y) * 0.5f;
        h.w = (t1.z - t1.w + u1.z - u1.w) * 0.5f;
        v.w = (t1.z + t1.w - u1.z - u1.w) * 0.5f;
        d.w = (t1.z - t1.w - u1.z + u1.w) * 0.5f;

        const size_t o4 = ((size_t)y1 * 512 + x1) >> 2;
        __stcs((float4*)outb +  0 * 65536 + o4, h);
        __stcs((float4*)outb +  1 * 65536 + o4, v);
        __stcs((float4*)outb +  2 * 65536 + o4, d);
    }

    __syncthreads();

    // ---- Phase C: half-pixel bilinear 2x, 4 horizontally-adjacent outputs ----
    // out[2k] = 0.25*v[k-1]+0.75*v[k],  out[2k+1] = 0.75*v[k]+0.25*v[k+1]
    #pragma unroll 1
    for (int i = tid; i < 1024; i += 256) {
        const int y  = i >> 4;          // 0..63
        const int xq = i & 15;          // group of 4 cols: x = 4*xq..4*xq+3
        const int ky = (y >> 1) + 1;    // local level-2 row of k
        const int ry0 = (y & 1) ? ky     : ky - 1;
        const int ry1 = (y & 1) ? ky + 1 : ky;
        const float wy0 = (y & 1) ? 0.75f : 0.25f;
        const float wy1 = 1.0f - wy0;

        const int cb = 2 * xq;          // local level-2 cols cb..cb+3 used

        const int A0 = ry0 * H2_S + cb;
        const int A1 = ry1 * H2_S + cb;

        float4 hv, vv, dv;
        {
            const float m0 = wy0 * sH[A0    ] + wy1 * sH[A1    ];
            const float m1 = wy0 * sH[A0 + 1] + wy1 * sH[A1 + 1];
            const float m2 = wy0 * sH[A0 + 2] + wy1 * sH[A1 + 2];
            const float m3 = wy0 * sH[A0 + 3] + wy1 * sH[A1 + 3];
            hv.x = 0.25f * m0 + 0.75f * m1;
            hv.y = 0.75f * m1 + 0.25f * m2;
            hv.z = 0.25f * m1 + 0.75f * m2;
            hv.w = 0.75f * m2 + 0.25f * m3;
        }
        {
            const float m0 = wy0 * sV[A0    ] + wy1 * sV[A1    ];
            const float m1 = wy0 * sV[A0 + 1] + wy1 * sV[A1 + 1];
            const float m2 = wy0 * sV[A0 + 2] + wy1 * sV[A1 + 2];
            const float m3 = wy0 * sV[A0 + 3] + wy1 * sV[A1 + 3];
            vv.x = 0.25f * m0 + 0.75f * m1;
            vv.y = 0.75f * m1 + 0.25f * m2;
            vv.z = 0.25f * m1 + 0.75f * m2;
            vv.w = 0.75f * m2 + 0.25f * m3;
        }
        {
            const float m0 = wy0 * sD[A0    ] + wy1 * sD[A1    ];
            const float m1 = wy0 * sD[A0 + 1] + wy1 * sD[A1 + 1];
            const float m2 = wy0 * sD[A0 + 2] + wy1 * sD[A1 + 2];
            const float m3 = wy0 * sD[A0 + 3] + wy1 * sD[A1 + 3];
            dv.x = 0.25f * m0 + 0.75f * m1;
            dv.y = 0.75f * m1 + 0.25f * m2;
            dv.z = 0.25f * m1 + 0.75f * m2;
            dv.w = 0.75f * m2 + 0.25f * m3;
        }

        const size_t o4 = ((size_t)(oy0 + y) * 512 + ox0 + 4 * xq) >> 2;
        __stcs((float4*)outb + 3 * 65536 + o4, hv);
        __stcs((float4*)outb + 4 * 65536 + o4, vv);
        __stcs((float4*)outb + 5 * 65536 + o4, dv);
    }
}

extern "C" void kernel_launch(void* const* d_in, const int* in_sizes, int n_in,
                              void* d_out, int out_size)
{
    const float* x = (const float*)d_in[0];
    float* out = (float*)d_out;
    dim3 grid(512 / TS, 512 / TS, 32);   // (8, 8, 32) = 2048 blocks
    dwt_fused_kernel<<<grid, 256>>>(x, out);
}

// round 4
// speedup vs baseline: 1.3973x; 1.0686x over previous
#include <cuda_runtime.h>

// DWTExtractor: 2-level Haar DWT + bilinear 2x upsample of level-2 details.
// Input:  (32, 1, 1024, 1024) fp32
// Output: (32, 6, 512, 512) fp32 = [cH1, cV1, cD1, up(cH2), up(cV2), up(cD2)]
//
// Each block: one 64x64 output tile (all 6 channels) for one batch image.
//   Merged phase: loop over the 34x34 level-2 grid (incl. 1-halo). Each cell
//     loads its 4x4 input patch ONCE (4 x LDG.128), produces:
//       - level-2 cH2/cV2/cD2 -> smem (edge clamping == jax resize renorm)
//       - for central 32x32 cells: the 2x2 block of level-1 cH1/cV1/cD1
//         -> gmem directly (float2 streaming stores).
//     Input is read exactly once (plus a thin halo ring).
//   (one __syncthreads)
//   Phase C: separable half-pixel bilinear 2x (0.75/0.25), 4 outputs/thread,
//     float4 streaming stores.

#define TS    64
#define H2_T  34
#define H2_S  35

__global__ __launch_bounds__(256, 6)
void dwt_fused_kernel(const float* __restrict__ in, float* __restrict__ out)
{
    __shared__ float sH[H2_T * H2_S];
    __shared__ float sV[H2_T * H2_S];
    __shared__ float sD[H2_T * H2_S];

    const int b   = blockIdx.z;
    const int oy0 = blockIdx.y * TS;
    const int ox0 = blockIdx.x * TS;
    const int tid = threadIdx.x;

    const float* __restrict__ inb  = in  + (size_t)b * 1024 * 1024;
    float* __restrict__       outb = out + (size_t)b * 6 * 512 * 512;

    // ---- Merged phase: level-2 (34x34 w/ halo) + level-1 (central) ----
    const int r0g = oy0 >> 1;   // level-2 tile origin on the 256-grid
    const int c0g = ox0 >> 1;
    #pragma unroll 1
    for (int i = tid; i < H2_T * H2_T; i += 256) {
        const int lr = i / H2_T;
        const int lc = i - lr * H2_T;
        const int rr = r0g - 1 + lr;
        const int cc = c0g - 1 + lc;
        const int r = min(max(rr, 0), 255);   // clamp only bites on halo cells
        const int c = min(max(cc, 0), 255);

        const float4 v0 = *((const float4*)(inb + (size_t)(4 * r    ) * 1024) + c);
        const float4 v1 = *((const float4*)(inb + (size_t)(4 * r + 1) * 1024) + c);
        const float4 v2 = *((const float4*)(inb + (size_t)(4 * r + 2) * 1024) + c);
        const float4 v3 = *((const float4*)(inb + (size_t)(4 * r + 3) * 1024) + c);

        // per-row horizontal sums/diffs
        const float s0l = v0.x + v0.y, d0l = v0.x - v0.y;
        const float s0r = v0.z + v0.w, d0r = v0.z - v0.w;
        const float s1l = v1.x + v1.y, d1l = v1.x - v1.y;
        const float s1r = v1.z + v1.w, d1r = v1.z - v1.w;
        const float s2l = v2.x + v2.y, d2l = v2.x - v2.y;
        const float s2r = v2.z + v2.w, d2r = v2.z - v2.w;
        const float s3l = v3.x + v3.y, d3l = v3.x - v3.y;
        const float s3r = v3.z + v3.w, d3r = v3.z - v3.w;

        // 2*cA1 quad
        const float a00 = s0l + s1l, a01 = s0r + s1r;
        const float a10 = s2l + s3l, a11 = s2r + s3r;

        // level-2 coeffs: 0.5 (haar) * 0.5 (cA1 factor folded) = 0.25
        sH[lr * H2_S + lc] = (a00 - a01 + a10 - a11) * 0.25f;
        sV[lr * H2_S + lc] = (a00 + a01 - a10 - a11) * 0.25f;
        sD[lr * H2_S + lc] = (a00 - a01 - a10 + a11) * 0.25f;

        // central cells: emit the 2x2 level-1 detail block (rows 2rr, 2rr+1;
        // cols 2cc, 2cc+1 on the 512-grid). lr,lc in [1,32] <=> unclamped.
        if ((unsigned)(lr - 1) < 32u && (unsigned)(lc - 1) < 32u) {
            const float2 hT = make_float2((d0l + d1l) * 0.5f, (d0r + d1r) * 0.5f);
            const float2 vT = make_float2((s0l - s1l) * 0.5f, (s0r - s1r) * 0.5f);
            const float2 dT = make_float2((d0l - d1l) * 0.5f, (d0r - d1r) * 0.5f);
            const float2 hB = make_float2((d2l + d3l) * 0.5f, (d2r + d3r) * 0.5f);
            const float2 vB = make_float2((s2l - s3l) * 0.5f, (s2r - s3r) * 0.5f);
            const float2 dB = make_float2((d2l - d3l) * 0.5f, (d2r - d3r) * 0.5f);

            const size_t oT = ((size_t)(2 * rr) * 512 + 2 * cc) >> 1;  // float2 idx
            const size_t oB = oT + 256;                                 // next row
            float2* o2 = (float2*)outb;
            __stcs(o2 + 0 * 131072 + oT, hT);
            __stcs(o2 + 0 * 131072 + oB, hB);
            __stcs(o2 + 1 * 131072 + oT, vT);
            __stcs(o2 + 1 * 131072 + oB, vB);
            __stcs(o2 + 2 * 131072 + oT, dT);
            __stcs(o2 + 2 * 131072 + oB, dB);
        }
    }

    __syncthreads();

    // ---- Phase C: half-pixel bilinear 2x, 4 horizontally-adjacent outputs ----
    // out[2k] = 0.25*v[k-1]+0.75*v[k],  out[2k+1] = 0.75*v[k]+0.25*v[k+1]
    #pragma unroll 1
    for (int i = tid; i < 1024; i += 256) {
        const int y  = i >> 4;          // 0..63
        const int xq = i & 15;          // group of 4 cols
        const int ky = (y >> 1) + 1;    // local level-2 row of k
        const int ry0 = (y & 1) ? ky     : ky - 1;
        const int ry1 = (y & 1) ? ky + 1 : ky;
        const float wy0 = (y & 1) ? 0.75f : 0.25f;
        const float wy1 = 1.0f - wy0;

        const int cb = 2 * xq;
        const int A0 = ry0 * H2_S + cb;
        const int A1 = ry1 * H2_S + cb;

        float4 hv, vv, dv;
        {
            const float m0 = wy0 * sH[A0    ] + wy1 * sH[A1    ];
            const float m1 = wy0 * sH[A0 + 1] + wy1 * sH[A1 + 1];
            const float m2 = wy0 * sH[A0 + 2] + wy1 * sH[A1 + 2];
            const float m3 = wy0 * sH[A0 + 3] + wy1 * sH[A1 + 3];
            hv.x = 0.25f * m0 + 0.75f * m1;
            hv.y = 0.75f * m1 + 0.25f * m2;
            hv.z = 0.25f * m1 + 0.75f * m2;
            hv.w = 0.75f * m2 + 0.25f * m3;
        }
        {
            const float m0 = wy0 * sV[A0    ] + wy1 * sV[A1    ];
            const float m1 = wy0 * sV[A0 + 1] + wy1 * sV[A1 + 1];
            const float m2 = wy0 * sV[A0 + 2] + wy1 * sV[A1 + 2];
            const float m3 = wy0 * sV[A0 + 3] + wy1 * sV[A1 + 3];
            vv.x = 0.25f * m0 + 0.75f * m1;
            vv.y = 0.75f * m1 + 0.25f * m2;
            vv.z = 0.25f * m1 + 0.75f * m2;
            vv.w = 0.75f * m2 + 0.25f * m3;
        }
        {
            const float m0 = wy0 * sD[A0    ] + wy1 * sD[A1    ];
            const float m1 = wy0 * sD[A0 + 1] + wy1 * sD[A1 + 1];
            const float m2 = wy0 * sD[A0 + 2] + wy1 * sD[A1 + 2];
            const float m3 = wy0 * sD[A0 + 3] + wy1 * sD[A1 + 3];
            dv.x = 0.25f * m0 + 0.75f * m1;
            dv.y = 0.75f * m1 + 0.25f * m2;
            dv.z = 0.25f * m1 + 0.75f * m2;
            dv.w = 0.75f * m2 + 0.25f * m3;
        }

        const size_t o4 = ((size_t)(oy0 + y) * 512 + ox0 + 4 * xq) >> 2;
        __stcs((float4*)outb + 3 * 65536 + o4, hv);
        __stcs((float4*)outb + 4 * 65536 + o4, vv);
        __stcs((float4*)outb + 5 * 65536 + o4, dv);
    }
}

extern "C" void kernel_launch(void* const* d_in, const int* in_sizes, int n_in,
                              void* d_out, int out_size)
{
    const float* x = (const float*)d_in[0];
    float* out = (float*)d_out;
    dim3 grid(512 / TS, 512 / TS, 32);   // (8, 8, 32) = 2048 blocks
    dwt_fused_kernel<<<grid, 256>>>(x, out);
}